// round 9
// baseline (speedup 1.0000x reference)
#include <cuda_runtime.h>
#include <cuda_bf16.h>
#include <cstdint>

// Fixed problem shapes
#define H_DIM 64
#define W_DIM 176
#define D_DIM 112
#define D4    (D_DIM / 4)          // 28 float4 chunks per feature row
#define CH    (H_DIM - 1)          // 63 cell rows
#define CW    (W_DIM - 1)          // 175 cell cols
#define NCELLS (CH * CW)           // 11025
#define CELLCAP 256                // max points per cell (mean ~45, Poisson)
#define GRP 16                     // points per pipeline group (4 rows per warp)

// Scratch (device globals; no runtime allocation allowed)
__device__ int    g_counts[NCELLS];                  // 44 KB (memset each run)
__device__ float4 g_meta[NCELLS * CELLCAP];          // 45 MB: (wx, wy, idx_bits, valid)

__device__ __forceinline__ void red_add_v4(float* addr, float a, float b, float c, float d) {
    asm volatile("red.global.add.v4.f32 [%0], {%1, %2, %3, %4};"
                 :: "l"(addr), "f"(a), "f"(b), "f"(c), "f"(d)
                 : "memory");
}

__device__ __forceinline__ void cp_async16(uint32_t smem_dst, const void* gsrc) {
    asm volatile("cp.async.cg.shared.global [%0], [%1], 16;"
                 :: "r"(smem_dst), "l"(gsrc) : "memory");
}
__device__ __forceinline__ void cp_commit() {
    asm volatile("cp.async.commit_group;" ::: "memory");
}
__device__ __forceinline__ void cp_wait1() {
    asm volatile("cp.async.wait_group 1;" ::: "memory");
}
__device__ __forceinline__ void cp_wait0() {
    asm volatile("cp.async.wait_group 0;" ::: "memory");
}

// ---------------------------------------------------------------- pass 1: fused bin (x4 ILP)
__global__ __launch_bounds__(256)
void bin_kernel(const float2* __restrict__ pos,
                const float4* __restrict__ feat,
                float* __restrict__ out,
                int n)
{
    // Block covers 1024 points; thread handles 4 strided (coalesced) points ->
    // 4 independent LDG -> ATOM -> STG chains overlap the atomic latency.
    const int base = blockIdx.x * 1024 + threadIdx.x;

    #pragma unroll
    for (int u = 0; u < 4; u++) {
        const int i = base + u * 256;
        if (i >= n) continue;

        const float2 p = pos[i];
        const float xf = floorf(p.x);
        const float yf = floorf(p.y);
        const int cx = min(max((int)xf, 0), CW - 1);
        const int cy = min(max((int)yf, 0), CH - 1);
        const float wx = p.x - xf;
        const float wy = p.y - yf;
        const int cell = cy * CW + cx;

        const int slot = atomicAdd(&g_counts[cell], 1);

        if (slot < CELLCAP) {
            g_meta[cell * CELLCAP + slot] = make_float4(wx, wy, __int_as_float(i), 1.0f);
        } else {
            // Overflow fallback (statistically never hit): direct scatter.
            const float w00 = (1.0f - wy) * (1.0f - wx);
            const float w01 = (1.0f - wy) * wx;
            const float w10 = wy * (1.0f - wx);
            const float w11 = wy * wx;
            const float4* frow = feat + (size_t)i * D4;
            float* o00 = out + ((size_t)(cy * W_DIM + cx) * D_DIM);
            float* o01 = o00 + D_DIM;
            float* o10 = o00 + (size_t)W_DIM * D_DIM;
            float* o11 = o10 + D_DIM;
            for (int k = 0; k < D4; k++) {
                const float4 f = frow[k];
                red_add_v4(o00 + k*4, w00*f.x, w00*f.y, w00*f.z, w00*f.w);
                red_add_v4(o01 + k*4, w01*f.x, w01*f.y, w01*f.z, w01*f.w);
                red_add_v4(o10 + k*4, w10*f.x, w10*f.y, w10*f.z, w10*f.w);
                red_add_v4(o11 + k*4, w11*f.x, w11*f.y, w11*f.z, w11*f.w);
            }
        }
    }
}

// ---------------------------------------------------------------- pass 2: CTA-per-cell gather
// Warp-private cp.async double-buffered pipeline: each warp stages its 4 rows
// of the next 16-point group into smem (no registers consumed by in-flight
// loads), consumes the current group from smem. Only __syncwarp-level sync.
__global__ __launch_bounds__(128, 10)
void cell_kernel(const float4* __restrict__ feat,
                 float* __restrict__ out)
{
    const int cell = blockIdx.x;
    const int warp = threadIdx.x >> 5;
    const int lane = threadIdx.x & 31;
    const int tid  = threadIdx.x;

    const int cnt = min(g_counts[cell], CELLCAP);
    if (cnt == 0) return;
    const int cnt_r = (cnt + GRP - 1) & ~(GRP - 1);
    const int G = cnt_r / GRP;                 // pipeline groups

    __shared__ float4 smeta[CELLCAP];          // 4 KB
    __shared__ float4 sbuf[2][GRP][D4];        // 14 KB (double-buffered feature rows)

    // Stage metadata (coalesced LDG.128, pads zeroed -> idx 0, weights 0).
    {
        const float4 z = make_float4(0.f, 0.f, 0.f, 0.f);
        const int base = cell * CELLCAP;
        for (int j = tid; j < cnt_r; j += 128)
            smeta[j] = (j < cnt) ? g_meta[base + j] : z;
    }
    __syncthreads();

    // Issue copies for group g into buffer b: warp w owns row slots w, w+4, w+8, w+12.
    // 112 copies of 16B per warp-group, spread over all 32 lanes.
    auto issue_group = [&](int g, int b) {
        #pragma unroll
        for (int c = lane; c < 4 * D4; c += 32) {
            const int rr   = c / D4;           // 0..3
            const int ch   = c - rr * D4;      // 0..27
            const int slot = warp + rr * 4;    // row slot in group
            const int fi   = __float_as_int(smeta[g * GRP + slot].z);
            const float4* src = feat + fi * D4 + ch;
            const uint32_t dst = (uint32_t)__cvta_generic_to_shared(&sbuf[b][slot][ch]);
            cp_async16(dst, src);
        }
        cp_commit();
    };

    const bool active = (lane < D4);
    float4 s   = {0,0,0,0};   // Σ valid * f
    float4 sx  = {0,0,0,0};   // Σ wx * f
    float4 sy  = {0,0,0,0};   // Σ wy * f
    float4 sp  = {0,0,0,0};   // Σ wx*wy * f

    issue_group(0, 0);

    for (int g = 0; g < G; g++) {
        const int b = g & 1;
        if (g + 1 < G) {
            issue_group(g + 1, (g + 1) & 1);
            cp_wait1();                        // group g complete (next still flying)
        } else {
            cp_wait0();
        }
        __syncwarp();                          // lanes see each other's staged rows

        #pragma unroll
        for (int rr = 0; rr < 4; rr++) {
            const int slot = warp + rr * 4;
            const float4 m = smeta[g * GRP + slot];
            float4 f = {0,0,0,0};
            if (active) f = sbuf[b][slot][lane];
            const float pxy = m.x * m.y;
            s.x  += m.w * f.x; s.y  += m.w * f.y; s.z  += m.w * f.z; s.w  += m.w * f.w;
            sx.x += m.x * f.x; sx.y += m.x * f.y; sx.z += m.x * f.z; sx.w += m.x * f.w;
            sy.x += m.y * f.x; sy.y += m.y * f.y; sy.z += m.y * f.z; sy.w += m.y * f.w;
            sp.x += pxy * f.x; sp.y += pxy * f.y; sp.z += pxy * f.z; sp.w += pxy * f.w;
        }
        __syncwarp();                          // done reading buf before re-issue at g+2
    }

    // All warps done -> reuse sbuf[0] as the cross-warp reduction buffer (7 KB fits).
    __syncthreads();
    float4 (*sred)[4][D4] = reinterpret_cast<float4 (*)[4][D4]>(&sbuf[0][0][0]);

    if (active) {
        float4 a00, a01, a10, a11;
        a11 = sp;
        a01 = make_float4(sx.x - sp.x, sx.y - sp.y, sx.z - sp.z, sx.w - sp.w);
        a10 = make_float4(sy.x - sp.x, sy.y - sp.y, sy.z - sp.z, sy.w - sp.w);
        a00 = make_float4(s.x - sx.x - sy.x + sp.x, s.y - sx.y - sy.y + sp.y,
                          s.z - sx.z - sy.z + sp.z, s.w - sx.w - sy.w + sp.w);
        sred[warp][0][lane] = a00;
        sred[warp][1][lane] = a01;
        sred[warp][2][lane] = a10;
        sred[warp][3][lane] = a11;
    }
    __syncthreads();

    // 112 threads: thread t -> corner t/28, chunk t%28. One RED.v4 each.
    if (tid < 4 * D4) {
        const int c = tid / D4;
        const int k = tid - c * D4;
        const float4 v0 = sred[0][c][k], v1 = sred[1][c][k];
        const float4 v2 = sred[2][c][k], v3 = sred[3][c][k];
        const float vx = v0.x + v1.x + v2.x + v3.x;
        const float vy = v0.y + v1.y + v2.y + v3.y;
        const float vz = v0.z + v1.z + v2.z + v3.z;
        const float vw = v0.w + v1.w + v2.w + v3.w;
        const int cy = cell / CW;
        const int cx = cell - cy * CW;
        const int dy = c >> 1, dx = c & 1;
        float* addr = out + ((size_t)((cy + dy) * W_DIM + (cx + dx)) * D_DIM + k * 4);
        red_add_v4(addr, vx, vy, vz, vw);
    }
}

// ---------------------------------------------------------------- launch
extern "C" void kernel_launch(void* const* d_in, const int* in_sizes, int n_in,
                              void* d_out, int out_size)
{
    const float2* pos  = (const float2*)d_in[0];
    const float4* feat = (const float4*)d_in[1];
    float* out = (float*)d_out;
    const int n = in_sizes[0] / 2;

    void* counts_ptr = nullptr;
    cudaGetSymbolAddress(&counts_ptr, g_counts);

    cudaMemsetAsync(out, 0, (size_t)out_size * sizeof(float));
    cudaMemsetAsync(counts_ptr, 0, sizeof(int) * NCELLS);

    bin_kernel<<<(n + 1023) / 1024, 256>>>(pos, feat, out, n);
    cell_kernel<<<NCELLS, 128>>>(feat, out);
}

// round 10
// speedup vs baseline: 1.6760x; 1.6760x over previous
#include <cuda_runtime.h>
#include <cuda_bf16.h>
#include <cstdint>

// Fixed problem shapes
#define H_DIM 64
#define W_DIM 176
#define D_DIM 112
#define D4    (D_DIM / 4)          // 28 float4 chunks per feature row
#define CH    (H_DIM - 1)          // 63 cell rows
#define CW    (W_DIM - 1)          // 175 cell cols
#define NCELLS (CH * CW)           // 11025
#define CELLCAP 256                // max points per cell (mean ~45, Poisson)

// Scratch (device globals; zero-initialized at load; cell_kernel self-resets
// g_counts so no per-launch memset is needed)
__device__ int    g_counts[NCELLS];
__device__ float4 g_meta[NCELLS * CELLCAP];          // (wx, wy, idx_bits, valid)

__device__ __forceinline__ void red_add_v4(float* addr, float a, float b, float c, float d) {
    asm volatile("red.global.add.v4.f32 [%0], {%1, %2, %3, %4};"
                 :: "l"(addr), "f"(a), "f"(b), "f"(c), "f"(d)
                 : "memory");
}

// ---------------------------------------------------------------- pass 1: fused bin + weight precompute
__global__ __launch_bounds__(256)
void bin_kernel(const float2* __restrict__ pos,
                const float4* __restrict__ feat,
                float* __restrict__ out,
                int n)
{
    const int i = blockIdx.x * blockDim.x + threadIdx.x;
    if (i >= n) return;

    const float2 p = pos[i];
    const float xf = floorf(p.x);
    const float yf = floorf(p.y);
    const int cx = min(max((int)xf, 0), CW - 1);
    const int cy = min(max((int)yf, 0), CH - 1);
    const float wx = p.x - xf;
    const float wy = p.y - yf;
    const int cell = cy * CW + cx;

    const int slot = atomicAdd(&g_counts[cell], 1);

    if (slot < CELLCAP) {
        g_meta[cell * CELLCAP + slot] = make_float4(wx, wy, __int_as_float(i), 1.0f);
    } else {
        // Overflow fallback (statistically never hit): direct scatter of this point.
        const float w00 = (1.0f - wy) * (1.0f - wx);
        const float w01 = (1.0f - wy) * wx;
        const float w10 = wy * (1.0f - wx);
        const float w11 = wy * wx;
        const float4* frow = feat + (size_t)i * D4;
        float* o00 = out + ((size_t)(cy * W_DIM + cx) * D_DIM);
        float* o01 = o00 + D_DIM;
        float* o10 = o00 + (size_t)W_DIM * D_DIM;
        float* o11 = o10 + D_DIM;
        for (int k = 0; k < D4; k++) {
            const float4 f = frow[k];
            red_add_v4(o00 + k*4, w00*f.x, w00*f.y, w00*f.z, w00*f.w);
            red_add_v4(o01 + k*4, w01*f.x, w01*f.y, w01*f.z, w01*f.w);
            red_add_v4(o10 + k*4, w10*f.x, w10*f.y, w10*f.z, w10*f.w);
            red_add_v4(o11 + k*4, w11*f.x, w11*f.y, w11*f.z, w11*f.w);
        }
    }
}

// ---------------------------------------------------------------- pass 2: CTA-per-cell gather
// R7 structure: pooled cell list in smem; warp w processes entries w, w+4, ...
// (balanced). __launch_bounds__(128, 8) -> full reg budget, 4 feature float4s
// stay live (MLP=4). Basis accumulators; pads (all-zero meta) vanish.
// Self-resets g_counts[cell] for the next graph replay.
__global__ __launch_bounds__(128, 8)
void cell_kernel(const float4* __restrict__ feat,
                 float* __restrict__ out)
{
    const int cell = blockIdx.x;
    const int warp = threadIdx.x >> 5;
    const int lane = threadIdx.x & 31;
    const int tid  = threadIdx.x;

    const int cnt = min(g_counts[cell], CELLCAP);
    if (cnt == 0) return;                      // counter already 0 -> nothing to reset
    const int cnt_r = (cnt + 15) & ~15;        // multiple of 16 -> equal iters per warp

    __shared__ float4 smeta[CELLCAP];          // 4 KB
    __shared__ float4 sred[4][4][D4];          // 7 KB

    // Cooperative staging: coalesced LDG.128, pads zeroed.
    {
        const float4 z = make_float4(0.f, 0.f, 0.f, 0.f);
        const int base = cell * CELLCAP;
        for (int j = tid; j < cnt_r; j += 128)
            smeta[j] = (j < cnt) ? g_meta[base + j] : z;
    }
    __syncthreads();

    const bool active = (lane < D4);
    float4 s   = {0,0,0,0};   // Σ valid * f
    float4 sx  = {0,0,0,0};   // Σ wx * f
    float4 sy  = {0,0,0,0};   // Σ wy * f
    float4 sxy = {0,0,0,0};   // Σ wx*wy * f

    for (int j = warp; j < cnt_r; j += 16) {
        const float4 m0 = smeta[j];
        const float4 m1 = smeta[j + 4];
        const float4 m2 = smeta[j + 8];
        const float4 m3 = smeta[j + 12];
        const int i0 = __float_as_int(m0.z);
        const int i1 = __float_as_int(m1.z);
        const int i2 = __float_as_int(m2.z);
        const int i3 = __float_as_int(m3.z);
        float4 f0 = {0,0,0,0}, f1 = {0,0,0,0}, f2 = {0,0,0,0}, f3 = {0,0,0,0};
        if (active) {
            f0 = feat[(size_t)i0 * D4 + lane];
            f1 = feat[(size_t)i1 * D4 + lane];
            f2 = feat[(size_t)i2 * D4 + lane];
            f3 = feat[(size_t)i3 * D4 + lane];
        }
        {
            const float pxy = m0.x * m0.y;
            s.x   += m0.w * f0.x; s.y   += m0.w * f0.y; s.z   += m0.w * f0.z; s.w   += m0.w * f0.w;
            sx.x  += m0.x * f0.x; sx.y  += m0.x * f0.y; sx.z  += m0.x * f0.z; sx.w  += m0.x * f0.w;
            sy.x  += m0.y * f0.x; sy.y  += m0.y * f0.y; sy.z  += m0.y * f0.z; sy.w  += m0.y * f0.w;
            sxy.x += pxy  * f0.x; sxy.y += pxy  * f0.y; sxy.z += pxy  * f0.z; sxy.w += pxy  * f0.w;
        }
        {
            const float pxy = m1.x * m1.y;
            s.x   += m1.w * f1.x; s.y   += m1.w * f1.y; s.z   += m1.w * f1.z; s.w   += m1.w * f1.w;
            sx.x  += m1.x * f1.x; sx.y  += m1.x * f1.y; sx.z  += m1.x * f1.z; sx.w  += m1.x * f1.w;
            sy.x  += m1.y * f1.x; sy.y  += m1.y * f1.y; sy.z  += m1.y * f1.z; sy.w  += m1.y * f1.w;
            sxy.x += pxy  * f1.x; sxy.y += pxy  * f1.y; sxy.z += pxy  * f1.z; sxy.w += pxy  * f1.w;
        }
        {
            const float pxy = m2.x * m2.y;
            s.x   += m2.w * f2.x; s.y   += m2.w * f2.y; s.z   += m2.w * f2.z; s.w   += m2.w * f2.w;
            sx.x  += m2.x * f2.x; sx.y  += m2.x * f2.y; sx.z  += m2.x * f2.z; sx.w  += m2.x * f2.w;
            sy.x  += m2.y * f2.x; sy.y  += m2.y * f2.y; sy.z  += m2.y * f2.z; sy.w  += m2.y * f2.w;
            sxy.x += pxy  * f2.x; sxy.y += pxy  * f2.y; sxy.z += pxy  * f2.z; sxy.w += pxy  * f2.w;
        }
        {
            const float pxy = m3.x * m3.y;
            s.x   += m3.w * f3.x; s.y   += m3.w * f3.y; s.z   += m3.w * f3.z; s.w   += m3.w * f3.w;
            sx.x  += m3.x * f3.x; sx.y  += m3.x * f3.y; sx.z  += m3.x * f3.z; sx.w  += m3.x * f3.w;
            sy.x  += m3.y * f3.x; sy.y  += m3.y * f3.y; sy.z  += m3.y * f3.z; sy.w  += m3.y * f3.w;
            sxy.x += pxy  * f3.x; sxy.y += pxy  * f3.y; sxy.z += pxy  * f3.z; sxy.w += pxy  * f3.w;
        }
    }

    // Basis -> corner conversion (per warp, in registers), then cross-warp reduce.
    if (active) {
        float4 a00, a01, a10, a11;
        a11.x = sxy.x;                     a11.y = sxy.y;                     a11.z = sxy.z;                     a11.w = sxy.w;
        a01.x = sx.x - sxy.x;              a01.y = sx.y - sxy.y;              a01.z = sx.z - sxy.z;              a01.w = sx.w - sxy.w;
        a10.x = sy.x - sxy.x;              a10.y = sy.y - sxy.y;              a10.z = sy.z - sxy.z;              a10.w = sy.w - sxy.w;
        a00.x = s.x - sx.x - sy.x + sxy.x; a00.y = s.y - sx.y - sy.y + sxy.y;
        a00.z = s.z - sx.z - sy.z + sxy.z; a00.w = s.w - sx.w - sy.w + sxy.w;
        sred[warp][0][lane] = a00;
        sred[warp][1][lane] = a01;
        sred[warp][2][lane] = a10;
        sred[warp][3][lane] = a11;
    }
    __syncthreads();

    // Self-reset counter for next replay (ordered after every thread's read of
    // g_counts by the two barriers above; each CTA touches only its own cell).
    if (tid == 0) g_counts[cell] = 0;

    // 112 threads: thread t -> corner t/28, chunk t%28. One RED.v4 each.
    if (tid < 4 * D4) {
        const int c = tid / D4;
        const int k = tid - c * D4;
        const float4 v0 = sred[0][c][k], v1 = sred[1][c][k];
        const float4 v2 = sred[2][c][k], v3 = sred[3][c][k];
        const float vx = v0.x + v1.x + v2.x + v3.x;
        const float vy = v0.y + v1.y + v2.y + v3.y;
        const float vz = v0.z + v1.z + v2.z + v3.z;
        const float vw = v0.w + v1.w + v2.w + v3.w;
        const int cy = cell / CW;
        const int cx = cell - cy * CW;
        const int dy = c >> 1, dx = c & 1;
        float* addr = out + ((size_t)((cy + dy) * W_DIM + (cx + dx)) * D_DIM + k * 4);
        red_add_v4(addr, vx, vy, vz, vw);
    }
}

// ---------------------------------------------------------------- launch
extern "C" void kernel_launch(void* const* d_in, const int* in_sizes, int n_in,
                              void* d_out, int out_size)
{
    const float2* pos  = (const float2*)d_in[0];
    const float4* feat = (const float4*)d_in[1];
    float* out = (float*)d_out;
    const int n = in_sizes[0] / 2;

    cudaMemsetAsync(out, 0, (size_t)out_size * sizeof(float));

    bin_kernel<<<(n + 255) / 256, 256>>>(pos, feat, out, n);
    cell_kernel<<<NCELLS, 128>>>(feat, out);
}